// round 1
// baseline (speedup 1.0000x reference)
#include <cuda_runtime.h>
#include <math.h>

// Problem constants (fixed by reference setup_inputs)
constexpr int BATCH = 256;
constexpr int N0 = 2048;
constexpr int N1 = 4096;
constexpr int N2 = 8192;
constexpr float LAMB = 0.5f;
constexpr int MAX_ITERS = 64;

// Persistent state (device globals -- no allocation allowed)
__device__ float g_v0[BATCH * N0];
__device__ float g_t0[BATCH * N0];
__device__ float g_e0[BATCH * N0];
__device__ float g_v1[BATCH * N1];
__device__ float g_t1[BATCH * N1];
__device__ float g_e1[BATCH * N1];
__device__ float g_e2[BATCH * N2];
__device__ double g_loss[MAX_ITERS];

enum EpiKind { FWD1 = 0, ERR1 = 1, ERR2 = 2, UPD0 = 3, UPD1 = 4 };

// ---------------------------------------------------------------------------
// init: v0 = broadcast(memory), t0 = tanh(v0), e0 = 0, e1 = 0, losses = 0
// ---------------------------------------------------------------------------
__global__ void init_kernel(const float* __restrict__ memory) {
    int i0 = blockIdx.x * blockDim.x + threadIdx.x;
    int stride = gridDim.x * blockDim.x;
    if (i0 < MAX_ITERS) g_loss[i0] = 0.0;
    for (int idx = i0; idx < BATCH * N0; idx += stride) {
        float m = memory[idx & (N0 - 1)];
        g_v0[idx] = m;
        g_t0[idx] = tanhf(m);
        g_e0[idx] = 0.0f;
    }
    for (int idx = i0; idx < BATCH * N1; idx += stride) {
        g_e1[idx] = 0.0f;
    }
}

// ---------------------------------------------------------------------------
// Fused GEMM + epilogue.
//   NT GEMMs (FWD1/ERR1/ERR2):  C[b,n] = sum_k A[b,k] * Bmat[n*K + k]
//   NN GEMMs (UPD0/UPD1):       C[b,n] = sum_k A[b,k] * Bmat[k*N + n]
// 128x128 tile, BK=16, 256 threads, 8x8 per thread (2x2 quads of 4x4).
// All dims compile-time multiples of 128 -> no bounds checks.
// ---------------------------------------------------------------------------
template <int EPI>
__global__ __launch_bounds__(256)
void gemm_kernel(const float* __restrict__ Bmat,
                 const float* __restrict__ aux,   // memory (UPD0) / batch_inp (ERR2)
                 const float* __restrict__ lr_p,  // inf_lr (UPD0/UPD1)
                 int loss_idx)                    // -1 = no energy recording
{
    constexpr bool BT = (EPI == FWD1 || EPI == ERR1 || EPI == ERR2);
    constexpr int N = (EPI == FWD1 || EPI == ERR1) ? N1
                    : (EPI == ERR2) ? N2
                    : (EPI == UPD0) ? N0 : N1;
    constexpr int K = (EPI == FWD1 || EPI == ERR1) ? N0
                    : (EPI == ERR2) ? N1
                    : (EPI == UPD0) ? N1 : N2;

    const float* __restrict__ A =
        (EPI == FWD1 || EPI == ERR1) ? g_t0
        : (EPI == ERR2) ? g_t1
        : (EPI == UPD0) ? g_e1 : g_e2;

    __shared__ float As[16][128];
    __shared__ float Bs[16][128];

    const int tid = threadIdx.x;
    const int tx = tid & 15;
    const int ty = tid >> 4;
    const int bn = blockIdx.x * 128;
    const int bm = blockIdx.y * 128;

    float acc[2][2][4][4];
#pragma unroll
    for (int hm = 0; hm < 2; hm++)
#pragma unroll
        for (int hn = 0; hn < 2; hn++)
#pragma unroll
            for (int i = 0; i < 4; i++)
#pragma unroll
                for (int j = 0; j < 4; j++) acc[hm][hn][i][j] = 0.0f;

    for (int kt = 0; kt < K; kt += 16) {
        // A tile: rows (m) 128, cols (k) 16, lda = K. Transpose into As[k][m].
#pragma unroll
        for (int l = 0; l < 2; l++) {
            int f = tid + l * 256;       // 0..511 float4 id
            int r = f >> 2;              // 0..127
            int c = (f & 3) * 4;         // 0,4,8,12
            float4 v = *(const float4*)&A[(size_t)(bm + r) * K + kt + c];
            As[c + 0][r] = v.x;
            As[c + 1][r] = v.y;
            As[c + 2][r] = v.z;
            As[c + 3][r] = v.w;
        }
        if (BT) {
            // B tile: rows (n) 128, cols (k) 16, ldb = K. Transpose into Bs[k][n].
#pragma unroll
            for (int l = 0; l < 2; l++) {
                int f = tid + l * 256;
                int r = f >> 2;
                int c = (f & 3) * 4;
                float4 v = *(const float4*)&Bmat[(size_t)(bn + r) * K + kt + c];
                Bs[c + 0][r] = v.x;
                Bs[c + 1][r] = v.y;
                Bs[c + 2][r] = v.z;
                Bs[c + 3][r] = v.w;
            }
        } else {
            // B tile: rows (k) 16, cols (n) 128, ldb = N. Direct copy.
#pragma unroll
            for (int l = 0; l < 2; l++) {
                int f = tid + l * 256;
                int kr = f >> 5;             // 0..15
                int c = (f & 31) * 4;        // 0..124
                float4 v = *(const float4*)&Bmat[(size_t)(kt + kr) * N + bn + c];
                *(float4*)&Bs[kr][c] = v;
            }
        }
        __syncthreads();

#pragma unroll
        for (int kk = 0; kk < 16; kk++) {
            float4 a0 = *(const float4*)&As[kk][ty * 4];
            float4 a1 = *(const float4*)&As[kk][64 + ty * 4];
            float4 b0 = *(const float4*)&Bs[kk][tx * 4];
            float4 b1 = *(const float4*)&Bs[kk][64 + tx * 4];
            float a[2][4] = {{a0.x, a0.y, a0.z, a0.w}, {a1.x, a1.y, a1.z, a1.w}};
            float b[2][4] = {{b0.x, b0.y, b0.z, b0.w}, {b1.x, b1.y, b1.z, b1.w}};
#pragma unroll
            for (int hm = 0; hm < 2; hm++)
#pragma unroll
                for (int hn = 0; hn < 2; hn++)
#pragma unroll
                    for (int i = 0; i < 4; i++)
#pragma unroll
                        for (int j = 0; j < 4; j++)
                            acc[hm][hn][i][j] += a[hm][i] * b[hn][j];
        }
        __syncthreads();
    }

    // -------------------- epilogue --------------------
    float lr = 0.0f;
    if (EPI == UPD0 || EPI == UPD1) lr = *lr_p;
    float lsum = 0.0f;

#pragma unroll
    for (int hm = 0; hm < 2; hm++)
#pragma unroll
        for (int i = 0; i < 4; i++) {
            int row = bm + hm * 64 + ty * 4 + i;
#pragma unroll
            for (int hn = 0; hn < 2; hn++)
#pragma unroll
                for (int j = 0; j < 4; j++) {
                    int col = bn + hn * 64 + tx * 4 + j;
                    size_t idx = (size_t)row * N + col;
                    float p = acc[hm][hn][i][j];
                    if (EPI == FWD1) {
                        g_v1[idx] = p;
                        g_t1[idx] = tanhf(p);
                    } else if (EPI == ERR1) {
                        float e = g_v1[idx] - p;
                        g_e1[idx] = e;
                        lsum += e * e;
                    } else if (EPI == ERR2) {
                        float e = aux[idx] - p;
                        g_e2[idx] = e;
                        lsum += e * e;
                    } else if (EPI == UPD0) {
                        float v = g_v0[idx];
                        float e = g_e0[idx];
                        float t = g_t0[idx];
                        float sgn = (v > 0.0f) ? 1.0f : ((v < 0.0f) ? -1.0f : 0.0f);
                        float nv = v + lr * (-e - LAMB * sgn + (1.0f - t * t) * p);
                        nv = fmaxf(nv, 0.0f);
                        g_v0[idx] = nv;
                        g_t0[idx] = tanhf(nv);
                        float ne = nv - aux[col];
                        g_e0[idx] = ne;
                        lsum += ne * ne;
                    } else {  // UPD1
                        float v = g_v1[idx];
                        float e = g_e1[idx];
                        float t = g_t1[idx];
                        float nv = v + lr * (-e + (1.0f - t * t) * p);
                        nv = fmaxf(nv, 0.0f);
                        g_v1[idx] = nv;
                        g_t1[idx] = tanhf(nv);
                    }
                }
        }

    // energy reduction: one atomicAdd(double) per block
    if (EPI == ERR1 || EPI == ERR2 || EPI == UPD0) {
#pragma unroll
        for (int o = 16; o > 0; o >>= 1)
            lsum += __shfl_down_sync(0xffffffffu, lsum, o);
        __shared__ float wsum[8];
        if ((tid & 31) == 0) wsum[tid >> 5] = lsum;
        __syncthreads();
        if (tid < 8) {
            float s = wsum[tid];
#pragma unroll
            for (int o = 4; o > 0; o >>= 1)
                s += __shfl_down_sync(0xffu, s, o);
            if (tid == 0 && loss_idx >= 0)
                atomicAdd(&g_loss[loss_idx], (double)s);
        }
    }
}

__global__ void finalize_kernel(float* __restrict__ out, int n) {
    int i = threadIdx.x;
    if (i < n) out[i] = (float)(g_loss[i] * (100.0 / (double)BATCH));
}

// ---------------------------------------------------------------------------
// Launch sequence (graph-capturable: kernel launches only)
// Inputs (metadata order): batch_inp, W0, W1, memory, n_iters, inf_lr
// ---------------------------------------------------------------------------
extern "C" void kernel_launch(void* const* d_in, const int* in_sizes, int n_in,
                              void* d_out, int out_size) {
    const float* batch_inp = (const float*)d_in[0];
    const float* W0 = (const float*)d_in[1];
    const float* W1 = (const float*)d_in[2];
    const float* memory = (const float*)d_in[3];
    const float* inf_lr = (const float*)d_in[5];

    int n_iters = out_size;
    if (n_iters > MAX_ITERS) n_iters = MAX_ITERS;

    // init state
    init_kernel<<<296, 256>>>(memory);

    // v1 = t0 @ W0^T (e1 stays 0 exactly, matching reference bitwise)
    gemm_kernel<FWD1><<<dim3(N1 / 128, BATCH / 128), 256>>>(W0, nullptr, nullptr, -1);
    // e2 = batch_inp - t1 @ W1^T (no energy recorded for init)
    gemm_kernel<ERR2><<<dim3(N2 / 128, BATCH / 128), 256>>>(W1, batch_inp, nullptr, -1);

    for (int it = 0; it < n_iters; it++) {
        // v0 update (uses old e0,e1,t0) + new e0 + e0^2 energy
        gemm_kernel<UPD0><<<dim3(N0 / 128, BATCH / 128), 256>>>(W0, memory, inf_lr, it);
        // v1 update (uses old e1,e2,t1)
        gemm_kernel<UPD1><<<dim3(N1 / 128, BATCH / 128), 256>>>(W1, nullptr, inf_lr, -1);
        // e1 = v1 - tanh(v0) @ W0^T + e1^2 energy
        gemm_kernel<ERR1><<<dim3(N1 / 128, BATCH / 128), 256>>>(W0, nullptr, nullptr, it);
        // e2 = batch_inp - tanh(v1) @ W1^T + e2^2 energy
        gemm_kernel<ERR2><<<dim3(N2 / 128, BATCH / 128), 256>>>(W1, batch_inp, nullptr, it);
    }

    finalize_kernel<<<1, MAX_ITERS>>>((float*)d_out, n_iters);
}

// round 5
// speedup vs baseline: 1.5021x; 1.5021x over previous
#include <cuda_runtime.h>
#include <math.h>
#include <stdint.h>

// ---------------------------------------------------------------------------
// Problem constants
// ---------------------------------------------------------------------------
constexpr int BATCH = 256;
constexpr int N0 = 2048;
constexpr int N1 = 4096;
constexpr int N2 = 8192;
constexpr float LAMB = 0.5f;
constexpr int MAX_ITERS = 64;

// ---------------------------------------------------------------------------
// Persistent state (__device__ globals; identical set to the passing R1)
// ---------------------------------------------------------------------------
__device__ float g_v0[BATCH * N0], g_t0[BATCH * N0], g_e0[BATCH * N0];
__device__ float g_v1[BATCH * N1], g_t1[BATCH * N1], g_e1[BATCH * N1];
__device__ float g_e2[BATCH * N2];
__device__ double g_loss[MAX_ITERS];

// ---------------------------------------------------------------------------
// PTX helpers (baseline sm_80 features only; ptxas target is plain sm_103)
// ---------------------------------------------------------------------------
__device__ __forceinline__ uint32_t s2u(const void* p) {
    uint32_t a;
    asm("{ .reg .u64 t; cvta.to.shared.u64 t, %1; cvt.u32.u64 %0, t; }"
        : "=r"(a) : "l"(p));
    return a;
}
__device__ __forceinline__ void cp_async16(uint32_t saddr, const void* gaddr) {
    asm volatile("cp.async.cg.shared.global [%0], [%1], 16;"
                 :: "r"(saddr), "l"(gaddr) : "memory");
}
__device__ __forceinline__ void cp_commit() {
    asm volatile("cp.async.commit_group;" ::: "memory");
}
template <int N>
__device__ __forceinline__ void cp_wait() {
    asm volatile("cp.async.wait_group %0;" :: "n"(N) : "memory");
}
__device__ __forceinline__ void mma_tf32(float* d, const uint32_t* a, const uint32_t* b) {
    asm volatile(
        "mma.sync.aligned.m16n8k8.row.col.f32.tf32.tf32.f32 "
        "{%0,%1,%2,%3}, {%4,%5,%6,%7}, {%8,%9}, {%0,%1,%2,%3};"
        : "+f"(d[0]), "+f"(d[1]), "+f"(d[2]), "+f"(d[3])
        : "r"(a[0]), "r"(a[1]), "r"(a[2]), "r"(a[3]), "r"(b[0]), "r"(b[1]));
}
// split fp32 x into tf32 hi + tf32 lo (x ~= hi + lo, residual ~2^-22 |x|)
__device__ __forceinline__ void split_tf32(float x, uint32_t& h, uint32_t& l) {
    uint32_t hu;
    asm("cvt.rna.tf32.f32 %0, %1;" : "=r"(hu) : "f"(x));
    float hf = __uint_as_float(hu);
    uint32_t lu;
    asm("cvt.rna.tf32.f32 %0, %1;" : "=r"(lu) : "f"(x - hf));
    h = hu;
    l = lu;
}

// ---------------------------------------------------------------------------
// init: v0 = broadcast(memory), t0 = tanh(v0), e0 = 0, e1 = 0, losses = 0
// ---------------------------------------------------------------------------
__global__ void init_state_k(const float* __restrict__ memory) {
    int i0 = blockIdx.x * blockDim.x + threadIdx.x;
    int stride = gridDim.x * blockDim.x;
    if (i0 < MAX_ITERS) g_loss[i0] = 0.0;
    for (int i = i0; i < BATCH * N0; i += stride) {
        float m = memory[i & (N0 - 1)];
        g_v0[i] = m;
        g_t0[i] = tanhf(m);
        g_e0[i] = 0.0f;
    }
    for (int i = i0; i < BATCH * N1; i += stride) g_e1[i] = 0.0f;
}

// ---------------------------------------------------------------------------
// Fused GEMM + epilogue with on-the-fly 3xTF32 emulation (fp32-accurate).
//   BT path (FWD1/ERR1/ERR2): D[m,n] = sum_k A[m,k] * W[n*KF + k]
//   NN path (UPD0/UPD1):      D[m,n] = sum_k A[m,k] * W[k*NF + n]
// CTA tile 128x128, KC=32, 4-stage cp.async pipeline, 256 threads (8 warps,
// 2m x 4n, warp tile 64x32). Fragments split into tf32 hi/lo in registers;
// 3 MMA terms per logical MMA: Ah*Bh + Ah*Bl + Al*Bh.
// ---------------------------------------------------------------------------
enum { E_FWD1 = 0, E_ERR1, E_ERR2, E_UPD0, E_UPD1 };

constexpr int BM = 128, BN = 128, KC = 32, STG = 4;
constexpr int LDA = 36;    // A smem row stride (floats)
constexpr int LDBT = 36;   // B smem stride, BT path (rows = n)
constexpr int LDBN = 132;  // B smem stride, NN path (rows = k)
constexpr int ASZ = BM * LDA;       // 4608 floats
constexpr int BSZ_T = BN * LDBT;    // 4608 floats
constexpr int BSZ_N = KC * LDBN;    // 4224 floats

template <int EPI>
__global__ __launch_bounds__(256)
void pcn_gemm(const float* __restrict__ Wg,    // weight operand (raw harness array)
              const float* __restrict__ aux,   // memory (UPD0) / batch_inp (ERR2)
              const float* __restrict__ lr_p,  // inf_lr (UPD0/UPD1)
              int loss_idx) {
    constexpr bool BT = (EPI == E_FWD1 || EPI == E_ERR1 || EPI == E_ERR2);
    constexpr int NF = (EPI == E_FWD1 || EPI == E_ERR1 || EPI == E_UPD1) ? N1
                     : (EPI == E_ERR2) ? N2 : N0;
    constexpr int KF = (EPI == E_FWD1 || EPI == E_ERR1) ? N0
                     : (EPI == E_ERR2 || EPI == E_UPD0) ? N1 : N2;
    constexpr int NCH = KF / KC;
    constexpr int BSZ = BT ? BSZ_T : BSZ_N;
    constexpr int STAGE_F = ASZ + BSZ;
    constexpr bool HAS_LOSS = (EPI == E_ERR1 || EPI == E_ERR2 || EPI == E_UPD0);

    const float* __restrict__ Ag =
        (EPI == E_FWD1 || EPI == E_ERR1) ? g_t0
        : (EPI == E_ERR2) ? g_t1
        : (EPI == E_UPD0) ? g_e1 : g_e2;

    extern __shared__ float sm[];
    const uint32_t sb = s2u(sm);
    const int tid = threadIdx.x;
    const int wid = tid >> 5;
    const int lane = tid & 31;
    const int tq = lane >> 2;   // 0..7  (groupID)
    const int tr = lane & 3;    // 0..3  (threadID_in_group)
    const int wm = wid >> 2;    // 0..1
    const int wn = wid & 3;     // 0..3
    const int bm = blockIdx.y * BM;
    const int bn = blockIdx.x * BN;

    auto load_chunk = [&](int c, int st) {
        const int kt = c * KC;
        uint32_t sA = sb + (uint32_t)st * STAGE_F * 4;
        // A tile: 128 rows x 32 k (8 float4 segs per row)
#pragma unroll
        for (int i = 0; i < 4; i++) {
            int f = tid + i * 256;
            int row = f >> 3, seg = f & 7;
            cp_async16(sA + row * (LDA * 4) + seg * 16,
                       Ag + (size_t)(bm + row) * KF + kt + seg * 4);
        }
        uint32_t sB = sA + ASZ * 4;
        if (BT) {
            // B tile: 128 n-rows x 32 k
#pragma unroll
            for (int i = 0; i < 4; i++) {
                int f = tid + i * 256;
                int row = f >> 3, seg = f & 7;
                cp_async16(sB + row * (LDBT * 4) + seg * 16,
                           Wg + (size_t)(bn + row) * KF + kt + seg * 4);
            }
        } else {
            // B tile: 32 k-rows x 128 n
#pragma unroll
            for (int i = 0; i < 4; i++) {
                int f = tid + i * 256;
                int row = f >> 5, seg = f & 31;
                cp_async16(sB + row * (LDBN * 4) + seg * 16,
                           Wg + (size_t)(kt + row) * NF + bn + seg * 4);
            }
        }
        cp_commit();
    };

    float d[4][4][4];
#pragma unroll
    for (int mi = 0; mi < 4; mi++)
#pragma unroll
        for (int ni = 0; ni < 4; ni++)
#pragma unroll
            for (int r = 0; r < 4; r++) d[mi][ni][r] = 0.0f;

    // ---- prologue ----
#pragma unroll
    for (int s = 0; s < STG - 1; s++) load_chunk(s, s);

    // ---- mainloop ----
    for (int c = 0; c < NCH; c++) {
        cp_wait<STG - 2>();
        __syncthreads();
        int nc = c + STG - 1;
        if (nc < NCH) load_chunk(nc, nc % STG);
        else cp_commit();  // keep group accounting aligned

        const float* As = sm + (c % STG) * STAGE_F;
        const float* Bs = As + ASZ;
#pragma unroll
        for (int step = 0; step < KC / 8; step++) {
            const int kk = step * 8;
            uint32_t aH[4][4], aL[4][4];
#pragma unroll
            for (int mi = 0; mi < 4; mi++) {
                int r = wm * 64 + mi * 16 + tq;
                split_tf32(As[r * LDA + kk + tr],        aH[mi][0], aL[mi][0]);
                split_tf32(As[(r + 8) * LDA + kk + tr],  aH[mi][1], aL[mi][1]);
                split_tf32(As[r * LDA + kk + tr + 4],    aH[mi][2], aL[mi][2]);
                split_tf32(As[(r + 8) * LDA + kk + tr + 4], aH[mi][3], aL[mi][3]);
            }
            uint32_t bH[4][2], bL[4][2];
#pragma unroll
            for (int ni = 0; ni < 4; ni++) {
                int n = wn * 32 + ni * 8 + tq;
                float b0, b1;
                if (BT) {
                    b0 = Bs[n * LDBT + kk + tr];
                    b1 = Bs[n * LDBT + kk + tr + 4];
                } else {
                    b0 = Bs[(kk + tr) * LDBN + n];
                    b1 = Bs[(kk + tr + 4) * LDBN + n];
                }
                split_tf32(b0, bH[ni][0], bL[ni][0]);
                split_tf32(b1, bH[ni][1], bL[ni][1]);
            }
#pragma unroll
            for (int mi = 0; mi < 4; mi++)
#pragma unroll
                for (int ni = 0; ni < 4; ni++) {
                    mma_tf32(d[mi][ni], aH[mi], bH[ni]);
                    mma_tf32(d[mi][ni], aH[mi], bL[ni]);
                    mma_tf32(d[mi][ni], aL[mi], bH[ni]);
                }
        }
    }

    // ---- epilogue (state updates + per-iteration energy) ----
    float lr = 0.0f;
    if (EPI == E_UPD0 || EPI == E_UPD1) lr = *lr_p;
    float lsum = 0.0f;

#pragma unroll
    for (int mi = 0; mi < 4; mi++)
#pragma unroll
        for (int ni = 0; ni < 4; ni++)
#pragma unroll
            for (int half = 0; half < 2; half++) {
                int row = bm + wm * 64 + mi * 16 + tq + half * 8;
                int col = bn + wn * 32 + ni * 8 + tr * 2;
                size_t idx = (size_t)row * NF + col;
                float2 p = make_float2(d[mi][ni][half * 2], d[mi][ni][half * 2 + 1]);
                if (EPI == E_FWD1) {
                    *(float2*)&g_v1[idx] = p;
                    *(float2*)&g_t1[idx] = make_float2(tanhf(p.x), tanhf(p.y));
                } else if (EPI == E_ERR1) {
                    float2 v = *(const float2*)&g_v1[idx];
                    float2 e = make_float2(v.x - p.x, v.y - p.y);
                    *(float2*)&g_e1[idx] = e;
                    lsum += e.x * e.x + e.y * e.y;
                } else if (EPI == E_ERR2) {
                    float2 v = *(const float2*)&aux[idx];
                    float2 e = make_float2(v.x - p.x, v.y - p.y);
                    *(float2*)&g_e2[idx] = e;
                    lsum += e.x * e.x + e.y * e.y;
                } else if (EPI == E_UPD0) {
                    float2 v = *(const float2*)&g_v0[idx];
                    float2 e = *(const float2*)&g_e0[idx];
                    float2 t = *(const float2*)&g_t0[idx];
                    float2 mem = *(const float2*)&aux[col];
                    float sgx = (v.x > 0.f) ? 1.f : ((v.x < 0.f) ? -1.f : 0.f);
                    float sgy = (v.y > 0.f) ? 1.f : ((v.y < 0.f) ? -1.f : 0.f);
                    float nvx = fmaxf(v.x + lr * (-e.x - LAMB * sgx + (1.f - t.x * t.x) * p.x), 0.f);
                    float nvy = fmaxf(v.y + lr * (-e.y - LAMB * sgy + (1.f - t.y * t.y) * p.y), 0.f);
                    *(float2*)&g_v0[idx] = make_float2(nvx, nvy);
                    *(float2*)&g_t0[idx] = make_float2(tanhf(nvx), tanhf(nvy));
                    float nex = nvx - mem.x, ney = nvy - mem.y;
                    *(float2*)&g_e0[idx] = make_float2(nex, ney);
                    lsum += nex * nex + ney * ney;
                } else {  // E_UPD1
                    float2 v = *(const float2*)&g_v1[idx];
                    float2 e = *(const float2*)&g_e1[idx];
                    float2 t = *(const float2*)&g_t1[idx];
                    float nvx = fmaxf(v.x + lr * (-e.x + (1.f - t.x * t.x) * p.x), 0.f);
                    float nvy = fmaxf(v.y + lr * (-e.y + (1.f - t.y * t.y) * p.y), 0.f);
                    *(float2*)&g_v1[idx] = make_float2(nvx, nvy);
                    *(float2*)&g_t1[idx] = make_float2(tanhf(nvx), tanhf(nvy));
                }
            }

    if (HAS_LOSS) {
        __shared__ float wred[8];
#pragma unroll
        for (int o = 16; o > 0; o >>= 1)
            lsum += __shfl_down_sync(0xffffffffu, lsum, o);
        if (lane == 0) wred[wid] = lsum;
        __syncthreads();
        if (tid == 0 && loss_idx >= 0) {
            float s = 0.f;
#pragma unroll
            for (int w = 0; w < 8; w++) s += wred[w];
            atomicAdd(&g_loss[loss_idx], (double)s);
        }
    }
}

__global__ void finalize_kernel(float* __restrict__ out, int n) {
    int i = threadIdx.x;
    if (i < n) out[i] = (float)(g_loss[i] * (100.0 / (double)BATCH));
}

// ---------------------------------------------------------------------------
// Launch (graph-capturable: kernel launches only)
// Inputs: batch_inp, W0, W1, memory, n_iters, inf_lr
// ---------------------------------------------------------------------------
constexpr int SMEM_T = STG * (ASZ + BSZ_T) * 4;  // 147456
constexpr int SMEM_N = STG * (ASZ + BSZ_N) * 4;  // 141312

extern "C" void kernel_launch(void* const* d_in, const int* in_sizes, int n_in,
                              void* d_out, int out_size) {
    const float* batch_inp = (const float*)d_in[0];
    const float* W0 = (const float*)d_in[1];
    const float* W1 = (const float*)d_in[2];
    const float* memory = (const float*)d_in[3];
    const float* inf_lr = (const float*)d_in[5];

    int n_iters = out_size;
    if (n_iters > MAX_ITERS) n_iters = MAX_ITERS;

    cudaFuncSetAttribute(pcn_gemm<E_FWD1>, cudaFuncAttributeMaxDynamicSharedMemorySize, SMEM_T);
    cudaFuncSetAttribute(pcn_gemm<E_ERR1>, cudaFuncAttributeMaxDynamicSharedMemorySize, SMEM_T);
    cudaFuncSetAttribute(pcn_gemm<E_ERR2>, cudaFuncAttributeMaxDynamicSharedMemorySize, SMEM_T);
    cudaFuncSetAttribute(pcn_gemm<E_UPD0>, cudaFuncAttributeMaxDynamicSharedMemorySize, SMEM_N);
    cudaFuncSetAttribute(pcn_gemm<E_UPD1>, cudaFuncAttributeMaxDynamicSharedMemorySize, SMEM_N);

    init_state_k<<<512, 256>>>(memory);

    // v1 = tanh(v0) @ W0^T ; t1 = tanh(v1). e1 stays exactly 0.
    pcn_gemm<E_FWD1><<<dim3(N1 / BN, BATCH / BM), 256, SMEM_T>>>(W0, nullptr, nullptr, -1);
    // e2 = batch_inp - tanh(v1) @ W1^T (no loss recorded for init)
    pcn_gemm<E_ERR2><<<dim3(N2 / BN, BATCH / BM), 256, SMEM_T>>>(W1, batch_inp, nullptr, -1);

    for (int it = 0; it < n_iters; it++) {
        // v0 update (old e0,e1,t0) + new e0 + e0^2 energy
        pcn_gemm<E_UPD0><<<dim3(N0 / BN, BATCH / BM), 256, SMEM_N>>>(W0, memory, inf_lr, it);
        // v1 update (old e1,e2,t1)
        pcn_gemm<E_UPD1><<<dim3(N1 / BN, BATCH / BM), 256, SMEM_N>>>(W1, nullptr, inf_lr, -1);
        // e1 = v1 - tanh(v0) @ W0^T + e1^2 energy
        pcn_gemm<E_ERR1><<<dim3(N1 / BN, BATCH / BM), 256, SMEM_T>>>(W0, nullptr, nullptr, it);
        // e2 = batch_inp - tanh(v1) @ W1^T + e2^2 energy
        pcn_gemm<E_ERR2><<<dim3(N2 / BN, BATCH / BM), 256, SMEM_T>>>(W1, batch_inp, nullptr, it);
    }

    finalize_kernel<<<1, MAX_ITERS>>>((float*)d_out, n_iters);
}

// round 6
// speedup vs baseline: 2.3815x; 1.5854x over previous
#include <cuda_runtime.h>
#include <math.h>
#include <stdint.h>

// ---------------------------------------------------------------------------
// Problem constants
// ---------------------------------------------------------------------------
constexpr int BATCH = 256;
constexpr int N0 = 2048;
constexpr int N1 = 4096;
constexpr int N2 = 8192;
constexpr float LAMB = 0.5f;
constexpr int MAX_ITERS = 64;

// ---------------------------------------------------------------------------
// Persistent state
// ---------------------------------------------------------------------------
__device__ float g_v0[BATCH * N0], g_t0[BATCH * N0], g_e0[BATCH * N0];
__device__ float g_v1[BATCH * N1], g_t1[BATCH * N1], g_e1[BATCH * N1];
__device__ float g_e2[BATCH * N2];
__device__ double g_loss[MAX_ITERS];

// ---------------------------------------------------------------------------
// PTX helpers (baseline sm_80 features; ptxas target is plain sm_103)
// ---------------------------------------------------------------------------
__device__ __forceinline__ uint32_t s2u(const void* p) {
    uint32_t a;
    asm("{ .reg .u64 t; cvta.to.shared.u64 t, %1; cvt.u32.u64 %0, t; }"
        : "=r"(a) : "l"(p));
    return a;
}
__device__ __forceinline__ void cp_async16(uint32_t saddr, const void* gaddr) {
    asm volatile("cp.async.cg.shared.global [%0], [%1], 16;"
                 :: "r"(saddr), "l"(gaddr) : "memory");
}
__device__ __forceinline__ void cp_commit() {
    asm volatile("cp.async.commit_group;" ::: "memory");
}
template <int N>
__device__ __forceinline__ void cp_wait() {
    asm volatile("cp.async.wait_group %0;" :: "n"(N) : "memory");
}
__device__ __forceinline__ void mma_tf32(float* d, const uint32_t* a, const uint32_t* b) {
    asm volatile(
        "mma.sync.aligned.m16n8k8.row.col.f32.tf32.tf32.f32 "
        "{%0,%1,%2,%3}, {%4,%5,%6,%7}, {%8,%9}, {%0,%1,%2,%3};"
        : "+f"(d[0]), "+f"(d[1]), "+f"(d[2]), "+f"(d[3])
        : "r"(a[0]), "r"(a[1]), "r"(a[2]), "r"(a[3]), "r"(b[0]), "r"(b[1]));
}
__device__ __forceinline__ void split_tf32(float x, uint32_t& h, uint32_t& l) {
    uint32_t hu;
    asm("cvt.rna.tf32.f32 %0, %1;" : "=r"(hu) : "f"(x));
    float hf = __uint_as_float(hu);
    uint32_t lu;
    asm("cvt.rna.tf32.f32 %0, %1;" : "=r"(lu) : "f"(x - hf));
    h = hu;
    l = lu;
}

// ---------------------------------------------------------------------------
// init
// ---------------------------------------------------------------------------
__global__ void init_state_k(const float* __restrict__ memory) {
    int i0 = blockIdx.x * blockDim.x + threadIdx.x;
    int stride = gridDim.x * blockDim.x;
    if (i0 < MAX_ITERS) g_loss[i0] = 0.0;
    for (int i = i0; i < BATCH * N0; i += stride) {
        float m = memory[i & (N0 - 1)];
        g_v0[i] = m;
        g_t0[i] = tanhf(m);
        g_e0[i] = 0.0f;
    }
    for (int i = i0; i < BATCH * N1; i += stride) g_e1[i] = 0.0f;
}

// ---------------------------------------------------------------------------
// Fused GEMM body, 3xTF32 on-the-fly emulation (fp32-accurate).
//   BT (FWD1/ERR1/ERR2): D[m,n] = sum_k A[m,k] * W[n*KF + k]
//   NN (UPD0/UPD1):      D[m,n] = sum_k A[m,k] * W[k*NF + n]
// CTA tile 64x64, KC=32, 3-stage cp.async, 128 threads (4 warps, 2m x 2n,
// warp tile 32x32). 4 CTAs/SM.
// ---------------------------------------------------------------------------
enum { E_FWD1 = 0, E_ERR1, E_ERR2, E_UPD0, E_UPD1 };

constexpr int BM = 64, BN = 64, KC = 32, STG = 3;
constexpr int LDA = 36;    // A smem row stride (floats), rows = m
constexpr int LDBT = 36;   // B smem stride, BT (rows = n)
constexpr int LDBN = 72;   // B smem stride, NN (rows = k); 72%32=8 -> conflict-free
constexpr int ASZ = BM * LDA;     // 2304 floats
constexpr int BSZ = 2304;         // BN*LDBT = KC*LDBN = 2304 floats (both paths)
constexpr int STAGE_F = ASZ + BSZ;            // 4608 floats
constexpr int SMEM_BYTES = STG * STAGE_F * 4; // 55296 B

template <int EPI>
__device__ __forceinline__ void gemm_body(
    int bx, int by,
    const float* __restrict__ Wg, const float* __restrict__ aux,
    const float* __restrict__ lr_p, int loss_idx)
{
    constexpr bool BT = (EPI == E_FWD1 || EPI == E_ERR1 || EPI == E_ERR2);
    constexpr int NF = (EPI == E_FWD1 || EPI == E_ERR1 || EPI == E_UPD1) ? N1
                     : (EPI == E_ERR2) ? N2 : N0;
    constexpr int KF = (EPI == E_FWD1 || EPI == E_ERR1) ? N0
                     : (EPI == E_ERR2 || EPI == E_UPD0) ? N1 : N2;
    constexpr int NCH = KF / KC;
    constexpr bool HAS_LOSS = (EPI == E_ERR1 || EPI == E_ERR2 || EPI == E_UPD0);

    const float* __restrict__ Ag =
        (EPI == E_FWD1 || EPI == E_ERR1) ? g_t0
        : (EPI == E_ERR2) ? g_t1
        : (EPI == E_UPD0) ? g_e1 : g_e2;

    extern __shared__ float sm[];
    const uint32_t sb = s2u(sm);
    const int tid = threadIdx.x;
    const int wid = tid >> 5;
    const int lane = tid & 31;
    const int tq = lane >> 2;   // 0..7
    const int tr = lane & 3;    // 0..3
    const int wm = wid >> 1;    // 0..1
    const int wn = wid & 1;     // 0..1
    const int bm = by * BM;
    const int bn = bx * BN;

    auto load_chunk = [&](int c, int st) {
        const int kt = c * KC;
        uint32_t sA = sb + (uint32_t)st * STAGE_F * 4;
        // A tile: 64 rows x 32 k
#pragma unroll
        for (int i = 0; i < 4; i++) {
            int f = tid + i * 128;
            int row = f >> 3, seg = f & 7;
            cp_async16(sA + row * (LDA * 4) + seg * 16,
                       Ag + (size_t)(bm + row) * KF + kt + seg * 4);
        }
        uint32_t sB = sA + ASZ * 4;
        if (BT) {
            // 64 n-rows x 32 k
#pragma unroll
            for (int i = 0; i < 4; i++) {
                int f = tid + i * 128;
                int row = f >> 3, seg = f & 7;
                cp_async16(sB + row * (LDBT * 4) + seg * 16,
                           Wg + (size_t)(bn + row) * KF + kt + seg * 4);
            }
        } else {
            // 32 k-rows x 64 n
#pragma unroll
            for (int i = 0; i < 4; i++) {
                int f = tid + i * 128;
                int row = f >> 4, seg = f & 15;
                cp_async16(sB + row * (LDBN * 4) + seg * 16,
                           Wg + (size_t)(kt + row) * NF + bn + seg * 4);
            }
        }
        cp_commit();
    };

    float d[2][4][4];
#pragma unroll
    for (int mi = 0; mi < 2; mi++)
#pragma unroll
        for (int ni = 0; ni < 4; ni++)
#pragma unroll
            for (int r = 0; r < 4; r++) d[mi][ni][r] = 0.0f;

#pragma unroll
    for (int s = 0; s < STG - 1; s++) load_chunk(s, s);

    for (int c = 0; c < NCH; c++) {
        cp_wait<STG - 2>();
        __syncthreads();
        int nc = c + STG - 1;
        if (nc < NCH) load_chunk(nc, nc % STG);
        else cp_commit();  // keep group accounting aligned

        const float* As = sm + (c % STG) * STAGE_F;
        const float* Bs = As + ASZ;
#pragma unroll
        for (int step = 0; step < KC / 8; step++) {
            const int kk = step * 8;
            uint32_t aH[2][4], aL[2][4];
#pragma unroll
            for (int mi = 0; mi < 2; mi++) {
                int r = wm * 32 + mi * 16 + tq;
                split_tf32(As[r * LDA + kk + tr],           aH[mi][0], aL[mi][0]);
                split_tf32(As[(r + 8) * LDA + kk + tr],     aH[mi][1], aL[mi][1]);
                split_tf32(As[r * LDA + kk + tr + 4],       aH[mi][2], aL[mi][2]);
                split_tf32(As[(r + 8) * LDA + kk + tr + 4], aH[mi][3], aL[mi][3]);
            }
            uint32_t bH[4][2], bL[4][2];
#pragma unroll
            for (int ni = 0; ni < 4; ni++) {
                int n = wn * 32 + ni * 8 + tq;
                float b0, b1;
                if (BT) {
                    b0 = Bs[n * LDBT + kk + tr];
                    b1 = Bs[n * LDBT + kk + tr + 4];
                } else {
                    b0 = Bs[(kk + tr) * LDBN + n];
                    b1 = Bs[(kk + tr + 4) * LDBN + n];
                }
                split_tf32(b0, bH[ni][0], bL[ni][0]);
                split_tf32(b1, bH[ni][1], bL[ni][1]);
            }
#pragma unroll
            for (int mi = 0; mi < 2; mi++)
#pragma unroll
                for (int ni = 0; ni < 4; ni++) {
                    mma_tf32(d[mi][ni], aH[mi], bH[ni]);
                    mma_tf32(d[mi][ni], aH[mi], bL[ni]);
                    mma_tf32(d[mi][ni], aL[mi], bH[ni]);
                }
        }
    }

    // ---- epilogue ----
    float lr = 0.0f;
    if (EPI == E_UPD0 || EPI == E_UPD1) lr = *lr_p;
    float lsum = 0.0f;

#pragma unroll
    for (int mi = 0; mi < 2; mi++)
#pragma unroll
        for (int ni = 0; ni < 4; ni++)
#pragma unroll
            for (int half = 0; half < 2; half++) {
                int row = bm + wm * 32 + mi * 16 + tq + half * 8;
                int col = bn + wn * 32 + ni * 8 + tr * 2;
                size_t idx = (size_t)row * NF + col;
                float2 p = make_float2(d[mi][ni][half * 2], d[mi][ni][half * 2 + 1]);
                if (EPI == E_FWD1) {
                    *(float2*)&g_v1[idx] = p;
                    *(float2*)&g_t1[idx] = make_float2(tanhf(p.x), tanhf(p.y));
                } else if (EPI == E_ERR1) {
                    float2 v = *(const float2*)&g_v1[idx];
                    float2 e = make_float2(v.x - p.x, v.y - p.y);
                    *(float2*)&g_e1[idx] = e;
                    lsum += e.x * e.x + e.y * e.y;
                } else if (EPI == E_ERR2) {
                    float2 v = *(const float2*)&aux[idx];
                    float2 e = make_float2(v.x - p.x, v.y - p.y);
                    *(float2*)&g_e2[idx] = e;
                    lsum += e.x * e.x + e.y * e.y;
                } else if (EPI == E_UPD0) {
                    float2 v = *(const float2*)&g_v0[idx];
                    float2 e = *(const float2*)&g_e0[idx];
                    float2 t = *(const float2*)&g_t0[idx];
                    float2 mem = *(const float2*)&aux[col];
                    float sgx = (v.x > 0.f) ? 1.f : ((v.x < 0.f) ? -1.f : 0.f);
                    float sgy = (v.y > 0.f) ? 1.f : ((v.y < 0.f) ? -1.f : 0.f);
                    float nvx = fmaxf(v.x + lr * (-e.x - LAMB * sgx + (1.f - t.x * t.x) * p.x), 0.f);
                    float nvy = fmaxf(v.y + lr * (-e.y - LAMB * sgy + (1.f - t.y * t.y) * p.y), 0.f);
                    *(float2*)&g_v0[idx] = make_float2(nvx, nvy);
                    *(float2*)&g_t0[idx] = make_float2(tanhf(nvx), tanhf(nvy));
                    float nex = nvx - mem.x, ney = nvy - mem.y;
                    *(float2*)&g_e0[idx] = make_float2(nex, ney);
                    lsum += nex * nex + ney * ney;
                } else {  // E_UPD1
                    float2 v = *(const float2*)&g_v1[idx];
                    float2 e = *(const float2*)&g_e1[idx];
                    float2 t = *(const float2*)&g_t1[idx];
                    float nvx = fmaxf(v.x + lr * (-e.x + (1.f - t.x * t.x) * p.x), 0.f);
                    float nvy = fmaxf(v.y + lr * (-e.y + (1.f - t.y * t.y) * p.y), 0.f);
                    *(float2*)&g_v1[idx] = make_float2(nvx, nvy);
                    *(float2*)&g_t1[idx] = make_float2(tanhf(nvx), tanhf(nvy));
                }
            }

    if (HAS_LOSS) {
        __shared__ float wred[4];
#pragma unroll
        for (int o = 16; o > 0; o >>= 1)
            lsum += __shfl_down_sync(0xffffffffu, lsum, o);
        if (lane == 0) wred[wid] = lsum;
        __syncthreads();
        if (tid == 0 && loss_idx >= 0) {
            float s = wred[0] + wred[1] + wred[2] + wred[3];
            atomicAdd(&g_loss[loss_idx], (double)s);
        }
    }
}

// ---------------------------------------------------------------------------
// Fused phase kernels (1-D grid, block decodes its sub-GEMM + tile coords)
// ---------------------------------------------------------------------------
constexpr int G_UPD0 = (N0 / BN) * (BATCH / BM);  // 32*4 = 128
constexpr int G_UPD1 = (N1 / BN) * (BATCH / BM);  // 64*4 = 256
constexpr int G_ERR1 = (N1 / BN) * (BATCH / BM);  // 256
constexpr int G_ERR2 = (N2 / BN) * (BATCH / BM);  // 512

__global__ __launch_bounds__(128, 4)
void upd_fused(const float* __restrict__ W0, const float* __restrict__ W1,
               const float* __restrict__ memory, const float* __restrict__ lr_p,
               int loss_idx) {
    int b = blockIdx.x;
    if (b < G_UPD0)
        gemm_body<E_UPD0>(b & 31, b >> 5, W0, memory, lr_p, loss_idx);
    else {
        int b2 = b - G_UPD0;
        gemm_body<E_UPD1>(b2 & 63, b2 >> 6, W1, nullptr, lr_p, -1);
    }
}

__global__ __launch_bounds__(128, 4)
void err_fused(const float* __restrict__ W0, const float* __restrict__ W1,
               const float* __restrict__ batch_inp, int loss_idx) {
    int b = blockIdx.x;
    if (b < G_ERR1)
        gemm_body<E_ERR1>(b & 63, b >> 6, W0, nullptr, nullptr, loss_idx);
    else {
        int b2 = b - G_ERR1;
        gemm_body<E_ERR2>(b2 & 127, b2 >> 7, W1, batch_inp, nullptr, loss_idx);
    }
}

__global__ __launch_bounds__(128, 4)
void fwd1_k(const float* __restrict__ W0) {
    gemm_body<E_FWD1>(blockIdx.x, blockIdx.y, W0, nullptr, nullptr, -1);
}

__global__ __launch_bounds__(128, 4)
void err2_init_k(const float* __restrict__ W1, const float* __restrict__ batch_inp) {
    gemm_body<E_ERR2>(blockIdx.x, blockIdx.y, W1, batch_inp, nullptr, -1);
}

__global__ void finalize_kernel(float* __restrict__ out, int n) {
    int i = threadIdx.x;
    if (i < n) out[i] = (float)(g_loss[i] * (100.0 / (double)BATCH));
}

// ---------------------------------------------------------------------------
// Launch (graph-capturable)
// Inputs: batch_inp, W0, W1, memory, n_iters, inf_lr
// ---------------------------------------------------------------------------
extern "C" void kernel_launch(void* const* d_in, const int* in_sizes, int n_in,
                              void* d_out, int out_size) {
    const float* batch_inp = (const float*)d_in[0];
    const float* W0 = (const float*)d_in[1];
    const float* W1 = (const float*)d_in[2];
    const float* memory = (const float*)d_in[3];
    const float* inf_lr = (const float*)d_in[5];

    int n_iters = out_size;
    if (n_iters > MAX_ITERS) n_iters = MAX_ITERS;

    cudaFuncSetAttribute(upd_fused, cudaFuncAttributeMaxDynamicSharedMemorySize, SMEM_BYTES);
    cudaFuncSetAttribute(err_fused, cudaFuncAttributeMaxDynamicSharedMemorySize, SMEM_BYTES);
    cudaFuncSetAttribute(fwd1_k, cudaFuncAttributeMaxDynamicSharedMemorySize, SMEM_BYTES);
    cudaFuncSetAttribute(err2_init_k, cudaFuncAttributeMaxDynamicSharedMemorySize, SMEM_BYTES);

    init_state_k<<<512, 256>>>(memory);

    // v1 = tanh(v0) @ W0^T; t1 = tanh(v1). e1 stays exactly 0.
    fwd1_k<<<dim3(N1 / BN, BATCH / BM), 128, SMEM_BYTES>>>(W0);
    // e2 = batch_inp - tanh(v1) @ W1^T (no loss recorded for init)
    err2_init_k<<<dim3(N2 / BN, BATCH / BM), 128, SMEM_BYTES>>>(W1, batch_inp);

    for (int it = 0; it < n_iters; it++) {
        upd_fused<<<G_UPD0 + G_UPD1, 128, SMEM_BYTES>>>(W0, W1, memory, inf_lr, it);
        err_fused<<<G_ERR1 + G_ERR2, 128, SMEM_BYTES>>>(W0, W1, batch_inp, it);
    }

    finalize_kernel<<<1, MAX_ITERS>>>((float*)d_out, n_iters);
}

// round 7
// speedup vs baseline: 2.8071x; 1.1787x over previous
#include <cuda_runtime.h>
#include <math.h>
#include <stdint.h>

// ---------------------------------------------------------------------------
// Problem constants
// ---------------------------------------------------------------------------
constexpr int BATCH = 256;
constexpr int N0 = 2048;
constexpr int N1 = 4096;
constexpr int N2 = 8192;
constexpr float LAMB = 0.5f;
constexpr int MAX_ITERS = 64;

// ---------------------------------------------------------------------------
// Persistent state + split-K scratch (__device__ globals)
// ---------------------------------------------------------------------------
__device__ float g_v0[BATCH * N0], g_t0[BATCH * N0], g_e0[BATCH * N0];
__device__ float g_v1[BATCH * N1], g_t1[BATCH * N1], g_e1[BATCH * N1];
__device__ float g_e2[BATCH * N2];
__device__ float sP0[2][BATCH * N0];   // e1@W0 partials (UPD0)
__device__ float sP1[4][BATCH * N1];   // e2@W1 partials (UPD1)
__device__ float sQ1[BATCH * N1];      // t0@W0^T (FWD1/ERR1)
__device__ float sQ2[2][BATCH * N2];   // t1@W1^T partials (ERR2)
__device__ double g_loss[MAX_ITERS];

// ---------------------------------------------------------------------------
// PTX helpers (sm_80 baseline; ptxas target is plain sm_103)
// ---------------------------------------------------------------------------
__device__ __forceinline__ uint32_t s2u(const void* p) {
    uint32_t a;
    asm("{ .reg .u64 t; cvta.to.shared.u64 t, %1; cvt.u32.u64 %0, t; }"
        : "=r"(a) : "l"(p));
    return a;
}
__device__ __forceinline__ void cp_async16(uint32_t saddr, const void* gaddr) {
    asm volatile("cp.async.cg.shared.global [%0], [%1], 16;"
                 :: "r"(saddr), "l"(gaddr) : "memory");
}
__device__ __forceinline__ void cp_commit() {
    asm volatile("cp.async.commit_group;" ::: "memory");
}
template <int N>
__device__ __forceinline__ void cp_wait() {
    asm volatile("cp.async.wait_group %0;" :: "n"(N) : "memory");
}
__device__ __forceinline__ void mma_tf32(float* d, const uint32_t* a, const uint32_t* b) {
    asm volatile(
        "mma.sync.aligned.m16n8k8.row.col.f32.tf32.tf32.f32 "
        "{%0,%1,%2,%3}, {%4,%5,%6,%7}, {%8,%9}, {%0,%1,%2,%3};"
        : "+f"(d[0]), "+f"(d[1]), "+f"(d[2]), "+f"(d[3])
        : "r"(a[0]), "r"(a[1]), "r"(a[2]), "r"(a[3]), "r"(b[0]), "r"(b[1]));
}
__device__ __forceinline__ void split_tf32(float x, uint32_t& h, uint32_t& l) {
    uint32_t hu;
    asm("cvt.rna.tf32.f32 %0, %1;" : "=r"(hu) : "f"(x));
    float hf = __uint_as_float(hu);
    uint32_t lu;
    asm("cvt.rna.tf32.f32 %0, %1;" : "=r"(lu) : "f"(x - hf));
    h = hu;
    l = lu;
}

// ---------------------------------------------------------------------------
// init
// ---------------------------------------------------------------------------
__global__ void init_state_k(const float* __restrict__ memory) {
    int i0 = blockIdx.x * blockDim.x + threadIdx.x;
    int stride = gridDim.x * blockDim.x;
    if (i0 < MAX_ITERS) g_loss[i0] = 0.0;
    for (int i = i0; i < BATCH * N0; i += stride) {
        float m = memory[i & (N0 - 1)];
        g_v0[i] = m;
        g_t0[i] = tanhf(m);
        g_e0[i] = 0.0f;
    }
    for (int i = i0; i < BATCH * N1; i += stride) g_e1[i] = 0.0f;
}

// ---------------------------------------------------------------------------
// Split-K GEMM (pure partial writer), 3xTF32 on-the-fly (fp32-accurate)
// CTA tile 64x64, 2 warps (each 32x64), KC=32, 3-stage cp.async, KPART=2048.
// Modes: 0: t0@W0^T -> sQ1     (BT, K=N0)
//        1: t1@W1^T -> sQ2[p]  (BT, K=N1, 2 parts)
//        2: e1@W0   -> sP0[p]  (NN, K=N1, 2 parts)
//        3: e2@W1   -> sP1[p]  (NN, K=N2, 4 parts)
// ---------------------------------------------------------------------------
constexpr int KC = 32, STG = 3, KPART = 2048;
constexpr int LDA = 36;    // A smem stride (rows = m)
constexpr int LDBT = 36;   // B smem stride, BT (rows = n)
constexpr int LDBN = 72;   // B smem stride, NN (rows = k)
constexpr int ASZ = 64 * LDA;                  // 2304 floats
constexpr int BSZ = 2304;                      // 64*36 = 32*72
constexpr int STAGE_F = ASZ + BSZ;             // 4608 floats
constexpr int SMEM_BYTES = STG * STAGE_F * 4;  // 55296 B

template <int MODE>
__device__ __forceinline__ void gemm_body(int bx, int by, int part,
                                          const float* __restrict__ Wg) {
    constexpr bool BT = (MODE == 0 || MODE == 1);
    constexpr int NF = (MODE == 0) ? N1 : (MODE == 1) ? N2 : (MODE == 2) ? N0 : N1;
    constexpr int KF = (MODE == 0) ? N0 : (MODE == 1) ? N1 : (MODE == 2) ? N1 : N2;
    constexpr int NCH = KPART / KC;  // 64

    const float* __restrict__ Ag =
        (MODE == 0) ? g_t0 : (MODE == 1) ? g_t1 : (MODE == 2) ? g_e1 : g_e2;
    float* __restrict__ dst =
        (MODE == 0) ? sQ1 : (MODE == 1) ? sQ2[part]
        : (MODE == 2) ? sP0[part] : sP1[part];

    extern __shared__ float sm[];
    const uint32_t sb = s2u(sm);
    const int tid = threadIdx.x;
    const int wid = tid >> 5;   // 0..1 (m-warp)
    const int lane = tid & 31;
    const int tq = lane >> 2;   // 0..7
    const int tr = lane & 3;    // 0..3
    const int bm = by * 64;
    const int bn = bx * 64;

    auto load_chunk = [&](int c, int st) {
        const int kt = part * KPART + c * KC;
        uint32_t sA = sb + (uint32_t)st * STAGE_F * 4;
#pragma unroll
        for (int i = 0; i < 8; i++) {
            int f = tid + i * 64;
            int row = f >> 3, seg = f & 7;
            cp_async16(sA + row * (LDA * 4) + seg * 16,
                       Ag + (size_t)(bm + row) * KF + kt + seg * 4);
        }
        uint32_t sB = sA + ASZ * 4;
        if (BT) {
#pragma unroll
            for (int i = 0; i < 8; i++) {
                int f = tid + i * 64;
                int row = f >> 3, seg = f & 7;
                cp_async16(sB + row * (LDBT * 4) + seg * 16,
                           Wg + (size_t)(bn + row) * KF + kt + seg * 4);
            }
        } else {
#pragma unroll
            for (int i = 0; i < 8; i++) {
                int f = tid + i * 64;
                int row = f >> 4, seg = f & 15;
                cp_async16(sB + row * (LDBN * 4) + seg * 16,
                           Wg + (size_t)(kt + row) * NF + bn + seg * 4);
            }
        }
        cp_commit();
    };

    float d[2][8][4];
#pragma unroll
    for (int mi = 0; mi < 2; mi++)
#pragma unroll
        for (int ni = 0; ni < 8; ni++)
#pragma unroll
            for (int r = 0; r < 4; r++) d[mi][ni][r] = 0.0f;

#pragma unroll
    for (int s = 0; s < STG - 1; s++) load_chunk(s, s);

    for (int c = 0; c < NCH; c++) {
        cp_wait<STG - 2>();
        __syncthreads();
        int nc = c + STG - 1;
        if (nc < NCH) load_chunk(nc, nc % STG);
        else cp_commit();  // keep group accounting aligned

        const float* As = sm + (c % STG) * STAGE_F;
        const float* Bs = As + ASZ;
#pragma unroll
        for (int step = 0; step < KC / 8; step++) {
            const int kk = step * 8;
            uint32_t aH[2][4], aL[2][4];
#pragma unroll
            for (int mi = 0; mi < 2; mi++) {
                int r = wid * 32 + mi * 16 + tq;
                split_tf32(As[r * LDA + kk + tr],           aH[mi][0], aL[mi][0]);
                split_tf32(As[(r + 8) * LDA + kk + tr],     aH[mi][1], aL[mi][1]);
                split_tf32(As[r * LDA + kk + tr + 4],       aH[mi][2], aL[mi][2]);
                split_tf32(As[(r + 8) * LDA + kk + tr + 4], aH[mi][3], aL[mi][3]);
            }
            uint32_t bH[8][2], bL[8][2];
#pragma unroll
            for (int ni = 0; ni < 8; ni++) {
                int n = ni * 8 + tq;
                float b0, b1;
                if (BT) {
                    b0 = Bs[n * LDBT + kk + tr];
                    b1 = Bs[n * LDBT + kk + tr + 4];
                } else {
                    b0 = Bs[(kk + tr) * LDBN + n];
                    b1 = Bs[(kk + tr + 4) * LDBN + n];
                }
                split_tf32(b0, bH[ni][0], bL[ni][0]);
                split_tf32(b1, bH[ni][1], bL[ni][1]);
            }
#pragma unroll
            for (int mi = 0; mi < 2; mi++)
#pragma unroll
                for (int ni = 0; ni < 8; ni++) {
                    mma_tf32(d[mi][ni], aH[mi], bH[ni]);
                    mma_tf32(d[mi][ni], aH[mi], bL[ni]);
                    mma_tf32(d[mi][ni], aL[mi], bH[ni]);
                }
        }
    }

    // write partial tile (plain stores; deterministic)
#pragma unroll
    for (int mi = 0; mi < 2; mi++)
#pragma unroll
        for (int ni = 0; ni < 8; ni++)
#pragma unroll
            for (int hf = 0; hf < 2; hf++) {
                int row = bm + wid * 32 + mi * 16 + tq + hf * 8;
                int col = bn + ni * 8 + tr * 2;
                *(float2*)&dst[(size_t)row * NF + col] =
                    make_float2(d[mi][ni][hf * 2], d[mi][ni][hf * 2 + 1]);
            }
}

// ---------------------------------------------------------------------------
// Fused phase GEMM kernels (1-D grid of uniform-duration CTAs)
// ---------------------------------------------------------------------------
// upd phase: MODE2 (2 parts x 128 tiles = 256) + MODE3 (4 parts x 256 = 1024)
__global__ __launch_bounds__(64, 4)
void upd_gemm(const float* __restrict__ W0, const float* __restrict__ W1) {
    int b = blockIdx.x;
    if (b < 256) {
        int part = b >> 7, t = b & 127;
        gemm_body<2>(t & 31, t >> 5, part, W0);
    } else {
        int b2 = b - 256;
        int part = b2 >> 8, t = b2 & 255;
        gemm_body<3>(t & 63, t >> 6, part, W1);
    }
}
// err phase: MODE0 (256 tiles) + MODE1 (2 parts x 512 = 1024); boff selects range
__global__ __launch_bounds__(64, 4)
void err_gemm(const float* __restrict__ W0, const float* __restrict__ W1, int boff) {
    int b = blockIdx.x + boff;
    if (b < 256) {
        gemm_body<0>(b & 63, b >> 6, 0, W0);
    } else {
        int b2 = b - 256;
        int part = b2 >> 9, t = b2 & 511;
        gemm_body<1>(t & 127, t >> 7, part, W1);
    }
}

// ---------------------------------------------------------------------------
// Epilogue kernels (elementwise, float4)
// ---------------------------------------------------------------------------
__device__ __forceinline__ void block_loss(float lsum, int loss_idx) {
    __shared__ float wred[8];
    int tid = threadIdx.x;
#pragma unroll
    for (int o = 16; o > 0; o >>= 1)
        lsum += __shfl_down_sync(0xffffffffu, lsum, o);
    if ((tid & 31) == 0) wred[tid >> 5] = lsum;
    __syncthreads();
    if (tid == 0 && loss_idx >= 0) {
        float s = 0.f;
#pragma unroll
        for (int w = 0; w < 8; w++) s += wred[w];
        atomicAdd(&g_loss[loss_idx], (double)s);
    }
}

// grid 1536 x 256 : v0 update (131072 f4) then v1 update (262144 f4)
__global__ __launch_bounds__(256)
void upd_epi(const float* __restrict__ memory, const float* __restrict__ lr_p,
             int loss_idx) {
    int i = blockIdx.x * blockDim.x + threadIdx.x;
    float lr = *lr_p;
    float lsum = 0.f;
    if (i < BATCH * N0 / 4) {
        float4 p0 = ((const float4*)sP0[0])[i];
        float4 p1 = ((const float4*)sP0[1])[i];
        float4 v4 = ((const float4*)g_v0)[i];
        float4 e4 = ((const float4*)g_e0)[i];
        float4 t4 = ((const float4*)g_t0)[i];
        float4 m4 = *(const float4*)&memory[(i * 4) & (N0 - 1)];
        float* p = &p0.x; float* pl = &p1.x;
        float* v = &v4.x; float* e = &e4.x; float* t = &t4.x; float* m = &m4.x;
        float4 nv4, nt4, ne4;
        float* nv = &nv4.x; float* nt = &nt4.x; float* ne = &ne4.x;
#pragma unroll
        for (int c = 0; c < 4; c++) {
            float g = p[c] + pl[c];
            float sg = (v[c] > 0.f) ? 1.f : ((v[c] < 0.f) ? -1.f : 0.f);
            float x = fmaxf(v[c] + lr * (-e[c] - LAMB * sg + (1.f - t[c] * t[c]) * g), 0.f);
            nv[c] = x;
            nt[c] = tanhf(x);
            float er = x - m[c];
            ne[c] = er;
            lsum += er * er;
        }
        ((float4*)g_v0)[i] = nv4;
        ((float4*)g_t0)[i] = nt4;
        ((float4*)g_e0)[i] = ne4;
    } else {
        int j = i - BATCH * N0 / 4;
        float4 p0 = ((const float4*)sP1[0])[j];
        float4 p1 = ((const float4*)sP1[1])[j];
        float4 p2 = ((const float4*)sP1[2])[j];
        float4 p3 = ((const float4*)sP1[3])[j];
        float4 v4 = ((const float4*)g_v1)[j];
        float4 e4 = ((const float4*)g_e1)[j];
        float4 t4 = ((const float4*)g_t1)[j];
        float* a0 = &p0.x; float* a1 = &p1.x; float* a2 = &p2.x; float* a3 = &p3.x;
        float* v = &v4.x; float* e = &e4.x; float* t = &t4.x;
        float4 nv4, nt4;
        float* nv = &nv4.x; float* nt = &nt4.x;
#pragma unroll
        for (int c = 0; c < 4; c++) {
            float g = (a0[c] + a1[c]) + (a2[c] + a3[c]);
            float x = fmaxf(v[c] + lr * (-e[c] + (1.f - t[c] * t[c]) * g), 0.f);
            nv[c] = x;
            nt[c] = tanhf(x);
        }
        ((float4*)g_v1)[j] = nv4;
        ((float4*)g_t1)[j] = nt4;
    }
    block_loss(lsum, loss_idx);
}

// grid 3072 x 256 : e1 (262144 f4, skipped when mode=1) then e2 (524288 f4)
__global__ __launch_bounds__(256)
void err_epi(const float* __restrict__ inp, int loss_idx, int mode) {
    int i = blockIdx.x * blockDim.x + threadIdx.x;
    float lsum = 0.f;
    if (i < BATCH * N1 / 4) {
        if (mode == 0) {
            float4 q = ((const float4*)sQ1)[i];
            float4 v = ((const float4*)g_v1)[i];
            float4 e = make_float4(v.x - q.x, v.y - q.y, v.z - q.z, v.w - q.w);
            ((float4*)g_e1)[i] = e;
            lsum = e.x * e.x + e.y * e.y + e.z * e.z + e.w * e.w;
        }
    } else {
        int j = i - BATCH * N1 / 4;
        float4 q0 = ((const float4*)sQ2[0])[j];
        float4 q1 = ((const float4*)sQ2[1])[j];
        float4 x = ((const float4*)inp)[j];
        float4 e = make_float4(x.x - (q0.x + q1.x), x.y - (q0.y + q1.y),
                               x.z - (q0.z + q1.z), x.w - (q0.w + q1.w));
        ((float4*)g_e2)[j] = e;
        lsum = e.x * e.x + e.y * e.y + e.z * e.z + e.w * e.w;
    }
    block_loss(lsum, loss_idx);
}

// grid 1024 x 256 : v1 = q1, t1 = tanh(q1)
__global__ __launch_bounds__(256)
void fwd_epi() {
    int i = blockIdx.x * blockDim.x + threadIdx.x;
    float4 q = ((const float4*)sQ1)[i];
    ((float4*)g_v1)[i] = q;
    float4 t = make_float4(tanhf(q.x), tanhf(q.y), tanhf(q.z), tanhf(q.w));
    ((float4*)g_t1)[i] = t;
}

__global__ void finalize_kernel(float* __restrict__ out, int n) {
    int i = threadIdx.x;
    if (i < n) out[i] = (float)(g_loss[i] * (100.0 / (double)BATCH));
}

// ---------------------------------------------------------------------------
// Launch (graph-capturable)
// Inputs: batch_inp, W0, W1, memory, n_iters, inf_lr
// ---------------------------------------------------------------------------
extern "C" void kernel_launch(void* const* d_in, const int* in_sizes, int n_in,
                              void* d_out, int out_size) {
    const float* batch_inp = (const float*)d_in[0];
    const float* W0 = (const float*)d_in[1];
    const float* W1 = (const float*)d_in[2];
    const float* memory = (const float*)d_in[3];
    const float* inf_lr = (const float*)d_in[5];

    int n_iters = out_size;
    if (n_iters > MAX_ITERS) n_iters = MAX_ITERS;

    cudaFuncSetAttribute(upd_gemm, cudaFuncAttributeMaxDynamicSharedMemorySize, SMEM_BYTES);
    cudaFuncSetAttribute(err_gemm, cudaFuncAttributeMaxDynamicSharedMemorySize, SMEM_BYTES);

    init_state_k<<<512, 256>>>(memory);

    // init: v1 = t0@W0^T, t1 = tanh(v1); e1 stays exactly 0; e2 = inp - t1@W1^T
    err_gemm<<<256, 64, SMEM_BYTES>>>(W0, W1, 0);      // mode 0 -> sQ1
    fwd_epi<<<1024, 256>>>();
    err_gemm<<<1024, 64, SMEM_BYTES>>>(W0, W1, 256);   // mode 1 -> sQ2
    err_epi<<<3072, 256>>>(batch_inp, -1, 1);          // e2 only, no loss

    for (int it = 0; it < n_iters; it++) {
        upd_gemm<<<1280, 64, SMEM_BYTES>>>(W0, W1);
        upd_epi<<<1536, 256>>>(memory, inf_lr, it);
        err_gemm<<<1280, 64, SMEM_BYTES>>>(W0, W1, 0);
        err_epi<<<3072, 256>>>(batch_inp, it, 0);
    }

    finalize_kernel<<<1, MAX_ITERS>>>((float*)d_out, n_iters);
}